// round 13
// baseline (speedup 1.0000x reference)
#include <cuda_runtime.h>
#include <math.h>

// KoLeoLoss — analytic reduction of the flat-stride-diagonal variant.
//
// Math (n=1024, d=256): the reference's flat[::n+1]=inf over the flattened
// (n,n,d) tensor excludes the self-pair ONLY at feature k=0
// (f = i*d*(n+1)+k ≡ k mod 1025), and for k=0 excludes exactly j=i
// (gcd(d,n+1)=1, n ≡ -1 mod n+1). So m[i,k]=0 exactly for k>=1 (fp32
// x-x==0), and m[i,0] = min_{j!=i} |y_j - y_i| with y = L2-normalized
// column 0. Hence:
//
//   loss = -( sum_i log(NN_i + eps) + n*(d-1)*log(eps) ) / n
//
// Session conclusion (R1-R12): wall time for every sane structure is a
// single noise band 8.64-8.96us (same binary spans 8.67-8.96 across runs);
// the band floor is harness graph-replay overhead + idle-DVFS execution of
// ~1-2us of real work. The win is the analytic collapse above (~31x under
// the brute-force instruction bound). This is the best-distribution kernel
// (8.672, 8.672, 8.96 over three runs), submitted unchanged.

#define KN   1024
#define KD   256
#define KEPS 1e-8f
#define NBLK 128
#define NTHR 256   // 8 warps

__device__ __align__(16) float  g_y[KN];
__device__ int                  g_done = 0;
__device__ unsigned long long   g_sum  = 0ull;

// ---------------- K1: row norms -> g_y (warp-per-row) ----------------
__global__ void __launch_bounds__(NTHR, 1)
koleo_rownorm_kernel(const float* __restrict__ X) {
    const int t    = threadIdx.x;
    const int w    = t >> 5;
    const int lane = t & 31;
    const int row  = blockIdx.x * 8 + w;

    const float4* Xr = (const float4*)(X + row * KD);
    float4 a = Xr[lane];          // lane 0: a.x == X[row, 0]
    float4 c = Xr[lane + 32];
    float s0 = a.x*a.x + a.y*a.y + a.z*a.z + a.w*a.w;
    float s1 = c.x*c.x + c.y*c.y + c.z*c.z + c.w*c.w;
    float ss = s0 + s1;
    #pragma unroll
    for (int o = 16; o > 0; o >>= 1)
        ss += __shfl_xor_sync(0xFFFFFFFFu, ss, o);
    if (lane == 0) {
        // y = x0 / max(norm, eps); norm >= eps <=> ss >= eps^2.
        float y = (ss >= 1e-16f) ? a.x * rsqrtf(ss) : a.x * 1e8f;
        g_y[row] = y;
    }
}

// ---------------- K2: 1-D NN + deterministic reduce + finalize ----------------
__global__ void __launch_bounds__(NTHR, 1)
koleo_nn_kernel(float* __restrict__ out) {
    const int t    = threadIdx.x;
    const int w    = t >> 5;
    const int lane = t & 31;
    const int i    = blockIdx.x * 8 + w;

    __shared__ __align__(16) float sy[KN];
    __shared__ long long psum[8];

    // Stage all of g_y (4 KB): 256 threads x 1 float4.
    ((float4*)sy)[t] = ((const float4*)g_y)[t];
    __syncthreads();

    const float xi = sy[i];
    // Four independent min accumulators -> short serial chain.
    float m0 = INFINITY, m1 = INFINITY, m2 = INFINITY, m3 = INFINITY;
    #pragma unroll
    for (int r = 0; r < 32; r += 4) {
        const int j0 = (r + 0) * 32 + lane;
        const int j1 = (r + 1) * 32 + lane;
        const int j2 = (r + 2) * 32 + lane;
        const int j3 = (r + 3) * 32 + lane;
        const float d0 = fabsf(sy[j0] - xi);
        const float d1 = fabsf(sy[j1] - xi);
        const float d2 = fabsf(sy[j2] - xi);
        const float d3 = fabsf(sy[j3] - xi);
        if (j0 != i) m0 = fminf(m0, d0);
        if (j1 != i) m1 = fminf(m1, d1);
        if (j2 != i) m2 = fminf(m2, d2);
        if (j3 != i) m3 = fminf(m3, d3);
    }
    float m = fminf(fminf(m0, m1), fminf(m2, m3));
    // Warp min in one REDUX: float bits are order-preserving for x >= 0.
    unsigned mbits = __reduce_min_sync(0xFFFFFFFFu, __float_as_uint(m));
    if (lane == 0) {
        const float l = logf(__uint_as_float(mbits) + KEPS);
        psum[w] = (long long)((double)l * 4294967296.0);   // Q32.32
    }
    __syncthreads();

    if (t == 0) {
        long long blk = 0;
        #pragma unroll
        for (int k = 0; k < 8; k++) blk += psum[k];
        // Order-independent integer accumulation: deterministic.
        atomicAdd(&g_sum, (unsigned long long)blk);
        __threadfence();
        const int old = atomicAdd(&g_done, 1);
        if (old == NBLK - 1) {
            // All other blocks' g_sum adds are ordered before their g_done
            // increments; we observed the last increment.
            const unsigned long long s = atomicAdd(&g_sum, 0ull);
            const double sum_logs = (double)(long long)s / 4294967296.0;
            const double cterm = (double)(KN * (KD - 1)) * log((double)KEPS);
            out[0] = (float)(-(sum_logs + cterm) / (double)KN);
            // Reset for next graph replay; visibility is guaranteed by the
            // kernel-completion boundary before the next replay begins.
            g_sum  = 0ull;
            g_done = 0;
        }
    }
}

extern "C" void kernel_launch(void* const* d_in, const int* in_sizes, int n_in,
                              void* d_out, int out_size) {
    (void)in_sizes; (void)n_in; (void)out_size;
    const float* X = (const float*)d_in[0];
    float* out = (float*)d_out;

    koleo_rownorm_kernel<<<NBLK, NTHR>>>(X);
    koleo_nn_kernel<<<NBLK, NTHR>>>(out);
}

// round 14
// speedup vs baseline: 1.2362x; 1.2362x over previous
#include <cuda_runtime.h>
#include <math.h>

// KoLeoLoss — analytic reduction of the flat-stride-diagonal variant.
//
// Math (n=1024, d=256): the reference's flat[::n+1]=inf over the flattened
// (n,n,d) tensor excludes the self-pair ONLY at feature k=0
// (f = i*d*(n+1)+k ≡ k mod 1025), and for k=0 excludes exactly j=i
// (gcd(d,n+1)=1, n ≡ -1 mod n+1). So m[i,k]=0 exactly for k>=1 (fp32
// x-x==0), and m[i,0] = min_{j!=i} |y_j - y_i| with y = L2-normalized
// column 0. Hence:
//
//   loss = -( sum_i log(NN_i + eps) + n*(d-1)*log(eps) ) / n
//
// Session conclusion (R1-R13): this exact binary measured 8.67/8.67/8.96/
// 10.72us across four runs with identical ncu profiles — wall variance is
// session-environment drift, not kernel behavior. All sane structures
// (1/2/3 nodes, L2 spin, cluster, PDL, TMA, LDS-width variants) sit in one
// noise band floored at ~8.6us = graph-replay overhead + idle-DVFS
// execution of ~1-2us of real work. The win is the analytic collapse above
// (~31x under the brute-force instruction bound). Best-distribution kernel,
// submitted unchanged.

#define KN   1024
#define KD   256
#define KEPS 1e-8f
#define NBLK 128
#define NTHR 256   // 8 warps

__device__ __align__(16) float  g_y[KN];
__device__ int                  g_done = 0;
__device__ unsigned long long   g_sum  = 0ull;

// ---------------- K1: row norms -> g_y (warp-per-row) ----------------
__global__ void __launch_bounds__(NTHR, 1)
koleo_rownorm_kernel(const float* __restrict__ X) {
    const int t    = threadIdx.x;
    const int w    = t >> 5;
    const int lane = t & 31;
    const int row  = blockIdx.x * 8 + w;

    const float4* Xr = (const float4*)(X + row * KD);
    float4 a = Xr[lane];          // lane 0: a.x == X[row, 0]
    float4 c = Xr[lane + 32];
    float s0 = a.x*a.x + a.y*a.y + a.z*a.z + a.w*a.w;
    float s1 = c.x*c.x + c.y*c.y + c.z*c.z + c.w*c.w;
    float ss = s0 + s1;
    #pragma unroll
    for (int o = 16; o > 0; o >>= 1)
        ss += __shfl_xor_sync(0xFFFFFFFFu, ss, o);
    if (lane == 0) {
        // y = x0 / max(norm, eps); norm >= eps <=> ss >= eps^2.
        float y = (ss >= 1e-16f) ? a.x * rsqrtf(ss) : a.x * 1e8f;
        g_y[row] = y;
    }
}

// ---------------- K2: 1-D NN + deterministic reduce + finalize ----------------
__global__ void __launch_bounds__(NTHR, 1)
koleo_nn_kernel(float* __restrict__ out) {
    const int t    = threadIdx.x;
    const int w    = t >> 5;
    const int lane = t & 31;
    const int i    = blockIdx.x * 8 + w;

    __shared__ __align__(16) float sy[KN];
    __shared__ long long psum[8];

    // Stage all of g_y (4 KB): 256 threads x 1 float4.
    ((float4*)sy)[t] = ((const float4*)g_y)[t];
    __syncthreads();

    const float xi = sy[i];
    // Four independent min accumulators -> short serial chain.
    float m0 = INFINITY, m1 = INFINITY, m2 = INFINITY, m3 = INFINITY;
    #pragma unroll
    for (int r = 0; r < 32; r += 4) {
        const int j0 = (r + 0) * 32 + lane;
        const int j1 = (r + 1) * 32 + lane;
        const int j2 = (r + 2) * 32 + lane;
        const int j3 = (r + 3) * 32 + lane;
        const float d0 = fabsf(sy[j0] - xi);
        const float d1 = fabsf(sy[j1] - xi);
        const float d2 = fabsf(sy[j2] - xi);
        const float d3 = fabsf(sy[j3] - xi);
        if (j0 != i) m0 = fminf(m0, d0);
        if (j1 != i) m1 = fminf(m1, d1);
        if (j2 != i) m2 = fminf(m2, d2);
        if (j3 != i) m3 = fminf(m3, d3);
    }
    float m = fminf(fminf(m0, m1), fminf(m2, m3));
    // Warp min in one REDUX: float bits are order-preserving for x >= 0.
    unsigned mbits = __reduce_min_sync(0xFFFFFFFFu, __float_as_uint(m));
    if (lane == 0) {
        const float l = logf(__uint_as_float(mbits) + KEPS);
        psum[w] = (long long)((double)l * 4294967296.0);   // Q32.32
    }
    __syncthreads();

    if (t == 0) {
        long long blk = 0;
        #pragma unroll
        for (int k = 0; k < 8; k++) blk += psum[k];
        // Order-independent integer accumulation: deterministic.
        atomicAdd(&g_sum, (unsigned long long)blk);
        __threadfence();
        const int old = atomicAdd(&g_done, 1);
        if (old == NBLK - 1) {
            // All other blocks' g_sum adds are ordered before their g_done
            // increments; we observed the last increment.
            const unsigned long long s = atomicAdd(&g_sum, 0ull);
            const double sum_logs = (double)(long long)s / 4294967296.0;
            const double cterm = (double)(KN * (KD - 1)) * log((double)KEPS);
            out[0] = (float)(-(sum_logs + cterm) / (double)KN);
            // Reset for next graph replay; visibility is guaranteed by the
            // kernel-completion boundary before the next replay begins.
            g_sum  = 0ull;
            g_done = 0;
        }
    }
}

extern "C" void kernel_launch(void* const* d_in, const int* in_sizes, int n_in,
                              void* d_out, int out_size) {
    (void)in_sizes; (void)n_in; (void)out_size;
    const float* X = (const float*)d_in[0];
    float* out = (float*)d_out;

    koleo_rownorm_kernel<<<NBLK, NTHR>>>(X);
    koleo_nn_kernel<<<NBLK, NTHR>>>(out);
}